// round 3
// baseline (speedup 1.0000x reference)
#include <cuda_runtime.h>

// ScoreMechain fused kernel — fp32, warp-per-sample, weights in shared.
// Mask dtype is auto-detected (uint8 vs 32-bit word) by a tiny pre-kernel,
// since the harness serializes the bool mask in an unspecified dtype.

#define FULL 0xffffffffu

constexpr int J  = 17;
constexpr int H  = 32;
constexpr int NQ = 8;
constexpr int NWARP = 12;
constexpr int NT = NWARP * 32;

// shared-memory float offsets
constexpr int OFF_WUP4 = 0;            // [8][544][4] packed quads over input dim
constexpr int OFF_WUPT = 17408;        // [544][2]   tail inputs i=32,33
constexpr int OFF_BUP  = 18496;        // [544]
constexpr int OFF_PB   = 19040;        // [544] pbias
constexpr int OFF_WUD  = 19584;        // [32][32]
constexpr int OFF_WQ   = 20608;
constexpr int OFF_WK   = 21632;
constexpr int OFF_WV   = 22656;
constexpr int OFF_WD1  = 23680;
constexpr int OFF_WD2  = 24704;
constexpr int OFF_BQ   = 25728;
constexpr int OFF_BK   = 25760;
constexpr int OFF_BV   = 25792;
constexpr int OFF_BD1  = 25824;
constexpr int OFF_BD2  = 25856;
constexpr int OFF_WS   = 25888;
constexpr int OFF_BS   = 25920;        // 1 float (+3 pad)
constexpr int OFF_WARP = 25924;        // per-warp scratch base
constexpr int WSTRIDE  = 1908;         // floats per warp
// per-warp layout: bufU[544] | bufA[544] | kpad[561](+3 pad) | misc[256]
constexpr int SMEM_FLOATS = OFF_WARP + NWARP * WSTRIDE;   // 48820 -> 195280 B

__device__ int g_mask_mode;   // 0 = uint8 per element, 1 = 32-bit word per element

__device__ __forceinline__ float leaky(float v) { return v > 0.f ? v : 0.01f * v; }

// Detect mask dtype: reference guarantees exactly 9 nonzero entries per 17-row.
__global__ void detect_mask_kernel(const void* __restrict__ mraw)
{
    const unsigned char* m8 = (const unsigned char*)mraw;
    int lane = threadIdx.x;   // 32 threads, samples 0..63, 2 per lane
    int bad8 = 0;
    #pragma unroll
    for (int s = 0; s < 2; s++) {
        int b = lane * 2 + s;
        int cnt = 0;
        for (int j = 0; j < J; j++) cnt += (m8[b * J + j] != 0);
        bad8 |= (cnt != 9);
    }
    unsigned any_bad = __ballot_sync(FULL, bad8);
    if (lane == 0) g_mask_mode = (any_bad == 0u) ? 0 : 1;
}

__global__ void __launch_bounds__(NT, 1)
score_mechain_kernel(const float* __restrict__ x,
                     const void* __restrict__ mraw,
                     const float* __restrict__ positions,
                     const float* __restrict__ W_up, const float* __restrict__ b_up,
                     const float* __restrict__ W_ud, const float* __restrict__ b_ud,
                     const float* __restrict__ W_q,  const float* __restrict__ b_q,
                     const float* __restrict__ W_k,  const float* __restrict__ b_k,
                     const float* __restrict__ W_v,  const float* __restrict__ b_v,
                     const float* __restrict__ W_d1, const float* __restrict__ b_d1,
                     const float* __restrict__ W_d2, const float* __restrict__ b_d2,
                     const float* __restrict__ W_s,  const float* __restrict__ b_s,
                     float* __restrict__ out, int B)
{
    extern __shared__ float smem[];
    const int tid = threadIdx.x;

    // ---------------- weight staging (once per CTA) ----------------
    for (int i = tid; i < 8 * 544 * 4; i += NT) {
        int iq = i / 2176, r = i % 2176, c = r >> 2, t = r & 3;
        smem[OFF_WUP4 + i] = W_up[(iq * 4 + t) * 544 + c];
    }
    for (int i = tid; i < 544 * 2; i += NT) {
        int c = i >> 1, t = i & 1;
        smem[OFF_WUPT + i] = W_up[(32 + t) * 544 + c];
    }
    for (int i = tid; i < 544; i += NT) smem[OFF_BUP + i] = b_up[i];
    for (int i = tid; i < 1024; i += NT) {
        smem[OFF_WUD + i] = W_ud[i];        // rows 0..31 of (64,32) row-major
        smem[OFF_WQ  + i] = W_q[i];
        smem[OFF_WK  + i] = W_k[i];
        smem[OFF_WV  + i] = W_v[i];
        smem[OFF_WD1 + i] = W_d1[i];
        smem[OFF_WD2 + i] = W_d2[i];
    }
    for (int i = tid; i < 32; i += NT) {
        smem[OFF_BQ  + i] = b_q[i];
        smem[OFF_BK  + i] = b_k[i];
        smem[OFF_BV  + i] = b_v[i];
        smem[OFF_BD1 + i] = b_d1[i];
        smem[OFF_BD2 + i] = b_d2[i];
        smem[OFF_WS  + i] = W_s[i];
    }
    if (tid == 0) smem[OFF_BS] = b_s[0];
    // pbias[j][o] = b_ud[o] + sum_h2 positions[j][h2] * W_ud[32+h2][o]
    for (int i = tid; i < 544; i += NT) {
        int j = i >> 5, o = i & 31;
        float acc = b_ud[o];
        #pragma unroll 8
        for (int h2 = 0; h2 < 32; h2++)
            acc += positions[j * 32 + h2] * W_ud[(32 + h2) * 32 + o];
        smem[OFF_PB + i] = acc;
    }
    __syncthreads();

    const int warpId = tid >> 5, lane = tid & 31;
    float* ws   = smem + OFF_WARP + warpId * WSTRIDE;
    float* bufU = ws;          // up values (17x32), needed through residual
    float* bufA = ws + 544;    // u, later overwritten with v
    float* kpad = ws + 1088;   // k padded (17x33), later o-scratch
    float* misc = ws + 1652;   // x(36) -> q(8x32) -> p(8x20) -> d1-out(8x32)

    const int gw = blockIdx.x * NWARP + warpId;
    const int nw = gridDim.x * NWARP;
    const float iscale = 0.17677669529663687f;  // 1/sqrt(32)

    // Mask read plan, resolved once per thread (uniform across warp):
    // mode 0: one byte per element; mode 1: one 32-bit word per element.
    const int mask_mode = g_mask_mode;
    const unsigned char* mbase = (const unsigned char*)mraw;
    const int melt = (mask_mode == 0) ? 1 : 4;   // bytes per element

    for (int b = gw; b < B; b += nw) {
        // ---- inputs ----
        const float* xp = x + b * 34;
        misc[lane] = xp[lane];
        if (lane < 4) misc[32 + lane] = (lane < 2) ? xp[32 + lane] : 0.f;
        unsigned mb = 1u;
        if (lane < J) {
            const unsigned char* mp = mbase + ((size_t)b * J + lane) * melt;
            unsigned v = mp[0];
            if (melt == 4) v |= mp[1] | mp[2] | mp[3];
            mb = (v != 0u);
        }
        unsigned occb = __ballot_sync(FULL, mb == 0u);   // occluded joints
        int occj[NQ];
        {
            unsigned tb = occb;
            #pragma unroll
            for (int t = 0; t < NQ; t++) { occj[t] = __ffs(tb) - 1; tb &= tb - 1; }
        }
        __syncwarp();

        // ---- up = leaky(x @ W_up + b_up) ----
        float acc[J];
        #pragma unroll
        for (int j = 0; j < J; j++) acc[j] = smem[OFF_BUP + j * 32 + lane];
        #pragma unroll
        for (int iq = 0; iq < 8; iq++) {
            float4 xq = *reinterpret_cast<const float4*>(misc + 4 * iq);
            #pragma unroll
            for (int j = 0; j < J; j++) {
                float4 w = *reinterpret_cast<const float4*>(
                    smem + OFF_WUP4 + (iq * 544 + j * 32 + lane) * 4);
                acc[j] += xq.x * w.x + xq.y * w.y + xq.z * w.z + xq.w * w.w;
            }
        }
        {
            float x32 = misc[32], x33 = misc[33];
            #pragma unroll
            for (int j = 0; j < J; j++) {
                float2 w = *reinterpret_cast<const float2*>(
                    smem + OFF_WUPT + (j * 32 + lane) * 2);
                acc[j] += x32 * w.x + x33 * w.y;
            }
        }
        #pragma unroll
        for (int j = 0; j < J; j++) bufU[j * 32 + lane] = leaky(acc[j]);
        __syncwarp();

        // ---- u = leaky(up @ Wud_top + pbias) ----
        #pragma unroll
        for (int j = 0; j < J; j++) acc[j] = smem[OFF_PB + j * 32 + lane];
        #pragma unroll
        for (int hq = 0; hq < 8; hq++) {
            float w0 = smem[OFF_WUD + (4 * hq + 0) * 32 + lane];
            float w1 = smem[OFF_WUD + (4 * hq + 1) * 32 + lane];
            float w2 = smem[OFF_WUD + (4 * hq + 2) * 32 + lane];
            float w3 = smem[OFF_WUD + (4 * hq + 3) * 32 + lane];
            #pragma unroll
            for (int j = 0; j < J; j++) {
                float4 a = *reinterpret_cast<const float4*>(bufU + j * 32 + 4 * hq);
                acc[j] += a.x * w0 + a.y * w1 + a.z * w2 + a.w * w3;
            }
        }
        #pragma unroll
        for (int j = 0; j < J; j++) bufA[j * 32 + lane] = leaky(acc[j]);
        __syncwarp();

        // ---- k, v (all joints) + q (occluded) ----
        float acck[J], accv[J], accq[NQ];
        #pragma unroll
        for (int j = 0; j < J; j++) {
            acck[j] = smem[OFF_BK + lane];
            accv[j] = smem[OFF_BV + lane];
        }
        #pragma unroll
        for (int t = 0; t < NQ; t++) accq[t] = smem[OFF_BQ + lane];
        #pragma unroll
        for (int hq = 0; hq < 8; hq++) {
            float wk0 = smem[OFF_WK + (4 * hq + 0) * 32 + lane];
            float wk1 = smem[OFF_WK + (4 * hq + 1) * 32 + lane];
            float wk2 = smem[OFF_WK + (4 * hq + 2) * 32 + lane];
            float wk3 = smem[OFF_WK + (4 * hq + 3) * 32 + lane];
            float wv0 = smem[OFF_WV + (4 * hq + 0) * 32 + lane];
            float wv1 = smem[OFF_WV + (4 * hq + 1) * 32 + lane];
            float wv2 = smem[OFF_WV + (4 * hq + 2) * 32 + lane];
            float wv3 = smem[OFF_WV + (4 * hq + 3) * 32 + lane];
            #pragma unroll
            for (int j = 0; j < J; j++) {
                float4 a = *reinterpret_cast<const float4*>(bufA + j * 32 + 4 * hq);
                acck[j] += a.x * wk0 + a.y * wk1 + a.z * wk2 + a.w * wk3;
                accv[j] += a.x * wv0 + a.y * wv1 + a.z * wv2 + a.w * wv3;
            }
            float wq0 = smem[OFF_WQ + (4 * hq + 0) * 32 + lane];
            float wq1 = smem[OFF_WQ + (4 * hq + 1) * 32 + lane];
            float wq2 = smem[OFF_WQ + (4 * hq + 2) * 32 + lane];
            float wq3 = smem[OFF_WQ + (4 * hq + 3) * 32 + lane];
            #pragma unroll
            for (int t = 0; t < NQ; t++) {
                float4 a = *reinterpret_cast<const float4*>(bufA + occj[t] * 32 + 4 * hq);
                accq[t] += a.x * wq0 + a.y * wq1 + a.z * wq2 + a.w * wq3;
            }
        }
        __syncwarp();   // all reads of u (bufA) done before overwrite with v
        #pragma unroll
        for (int j = 0; j < J; j++) {
            kpad[j * 33 + lane] = acck[j];
            bufA[j * 32 + lane] = accv[j];
        }
        float* qsh = misc;   // x is dead
        #pragma unroll
        for (int t = 0; t < NQ; t++) qsh[t * 32 + lane] = accq[t];
        __syncwarp();

        // ---- scores: lane = key joint ----
        float sc[NQ];
        #pragma unroll
        for (int t = 0; t < NQ; t++) sc[t] = 0.f;
        #pragma unroll 8
        for (int h = 0; h < 32; h++) {
            float kl = (lane < J) ? kpad[lane * 33 + h] : 0.f;
            #pragma unroll
            for (int t = 0; t < NQ; t++) sc[t] += qsh[t * 32 + h] * kl;
        }
        __syncwarp();   // q fully consumed; misc becomes p
        float* psh = misc;
        #pragma unroll
        for (int t = 0; t < NQ; t++) {
            float s_ = (lane < J) ? sc[t] * iscale : -1e30f;
            float mx = s_;
            #pragma unroll
            for (int o = 16; o > 0; o >>= 1)
                mx = fmaxf(mx, __shfl_xor_sync(FULL, mx, o));
            float e = (lane < J) ? __expf(s_ - mx) : 0.f;
            float sum = e;
            #pragma unroll
            for (int o = 16; o > 0; o >>= 1)
                sum += __shfl_xor_sync(FULL, sum, o);
            float pv = __fdividef(e, sum);
            if (lane < J) psh[t * 20 + lane] = pv;
        }
        __syncwarp();

        // ---- o = att @ v : lane = h ----
        float o8[NQ];
        #pragma unroll
        for (int t = 0; t < NQ; t++) o8[t] = 0.f;
        #pragma unroll
        for (int j = 0; j < J; j++) {
            float vj = bufA[j * 32 + lane];
            #pragma unroll
            for (int t = 0; t < NQ; t++) o8[t] += psh[t * 20 + j] * vj;
        }
        __syncwarp();   // k dead; kpad becomes o-scratch
        #pragma unroll
        for (int t = 0; t < NQ; t++) kpad[t * 32 + lane] = o8[t];
        __syncwarp();

        // ---- d1 ----
        float ad[NQ];
        #pragma unroll
        for (int t = 0; t < NQ; t++) ad[t] = smem[OFF_BD1 + lane];
        #pragma unroll
        for (int hq = 0; hq < 8; hq++) {
            float w0 = smem[OFF_WD1 + (4 * hq + 0) * 32 + lane];
            float w1 = smem[OFF_WD1 + (4 * hq + 1) * 32 + lane];
            float w2 = smem[OFF_WD1 + (4 * hq + 2) * 32 + lane];
            float w3 = smem[OFF_WD1 + (4 * hq + 3) * 32 + lane];
            #pragma unroll
            for (int t = 0; t < NQ; t++) {
                float4 a = *reinterpret_cast<const float4*>(kpad + t * 32 + 4 * hq);
                ad[t] += a.x * w0 + a.y * w1 + a.z * w2 + a.w * w3;
            }
        }
        __syncwarp();   // p dead; misc becomes d1 output
        #pragma unroll
        for (int t = 0; t < NQ; t++) misc[t * 32 + lane] = leaky(ad[t]);
        __syncwarp();

        // ---- d2 + residual ----
        float ae[NQ];
        #pragma unroll
        for (int t = 0; t < NQ; t++)
            ae[t] = smem[OFF_BD2 + lane] + bufU[occj[t] * 32 + lane];
        #pragma unroll
        for (int hq = 0; hq < 8; hq++) {
            float w0 = smem[OFF_WD2 + (4 * hq + 0) * 32 + lane];
            float w1 = smem[OFF_WD2 + (4 * hq + 1) * 32 + lane];
            float w2 = smem[OFF_WD2 + (4 * hq + 2) * 32 + lane];
            float w3 = smem[OFF_WD2 + (4 * hq + 3) * 32 + lane];
            #pragma unroll
            for (int t = 0; t < NQ; t++) {
                float4 a = *reinterpret_cast<const float4*>(misc + t * 32 + 4 * hq);
                ae[t] += a.x * w0 + a.y * w1 + a.z * w2 + a.w * w3;
            }
        }

        // ---- final: sigmoid(o @ W_s + b_s) ----
        float wsv = smem[OFF_WS + lane];
        float outval = 0.f;
        #pragma unroll
        for (int t = 0; t < NQ; t++) {
            float val = ae[t] * wsv;
            #pragma unroll
            for (int o = 16; o > 0; o >>= 1)
                val += __shfl_xor_sync(FULL, val, o);
            if (lane == t) outval = val;
        }
        if (lane < NQ) {
            float z = outval + smem[OFF_BS];
            out[b * NQ + lane] = __fdividef(1.f, 1.f + __expf(-z));
        }
        __syncwarp();   // scratch reused next iteration
    }
}

extern "C" void kernel_launch(void* const* d_in, const int* in_sizes, int n_in,
                              void* d_out, int out_size)
{
    const float* x         = (const float*)d_in[0];
    const void*  mraw      = d_in[1];
    const float* positions = (const float*)d_in[2];
    const float* W_up = (const float*)d_in[3];
    const float* b_up = (const float*)d_in[4];
    const float* W_ud = (const float*)d_in[5];
    const float* b_ud = (const float*)d_in[6];
    const float* W_q  = (const float*)d_in[7];
    const float* b_q  = (const float*)d_in[8];
    const float* W_k  = (const float*)d_in[9];
    const float* b_k  = (const float*)d_in[10];
    const float* W_v  = (const float*)d_in[11];
    const float* b_v  = (const float*)d_in[12];
    const float* W_d1 = (const float*)d_in[13];
    const float* b_d1 = (const float*)d_in[14];
    const float* W_d2 = (const float*)d_in[15];
    const float* b_d2 = (const float*)d_in[16];
    const float* W_s  = (const float*)d_in[17];
    const float* b_s  = (const float*)d_in[18];
    float* out = (float*)d_out;

    const int B = in_sizes[0] / 34;
    const size_t smem_bytes = (size_t)SMEM_FLOATS * sizeof(float);

    detect_mask_kernel<<<1, 32>>>(mraw);

    cudaFuncSetAttribute(score_mechain_kernel,
                         cudaFuncAttributeMaxDynamicSharedMemorySize,
                         (int)smem_bytes);
    score_mechain_kernel<<<148, NT, smem_bytes>>>(
        x, mraw, positions, W_up, b_up, W_ud, b_ud, W_q, b_q, W_k, b_k,
        W_v, b_v, W_d1, b_d1, W_d2, b_d2, W_s, b_s, out, B);
}